// round 4
// baseline (speedup 1.0000x reference)
#include <cuda_runtime.h>
#include <math.h>

// Problem constants
constexpr int B  = 4;
constexpr int N  = 2048;
constexpr int D  = 1024;     // model dim = K for projections
constexpr int H  = 16;
constexpr int DK = 64;
constexpr int HD = H * DK;   // 1024

// Scratch (device globals — no allocation allowed)
__device__ float g_Q[B * H * N * DK];    // [bh][n][d]
__device__ float g_K[B * H * N * DK];
__device__ float g_V[B * H * N * DK];
__device__ float g_att[B * N * HD];      // [b][n][h*DK]

// ---------------------------------------------------------------------------
// SGEMM 128x128x8, 256 threads, 8x8 register tile. K = 1024, N = 1024 fixed.
// ---------------------------------------------------------------------------
constexpr int BM = 128, BN = 128, BK = 8, TM = 8, TN = 8;

__device__ __forceinline__ void sgemm_body(const float* __restrict__ A,
                                           const float* __restrict__ W,
                                           float acc[TM][TN],
                                           int rowBase, int colBase) {
    __shared__ float As[BK][BM];
    __shared__ float Bs[BK][BN];

    const int tid = threadIdx.x;
    const int tx = tid & 15;
    const int ty = tid >> 4;

    const int aRow  = tid >> 1;          // 0..127
    const int aCol4 = (tid & 1) * 4;     // 0 or 4
    const int bRow  = tid >> 5;          // 0..7
    const int bCol4 = (tid & 31) * 4;    // 0..124

    for (int k0 = 0; k0 < D; k0 += BK) {
        float4 av = *reinterpret_cast<const float4*>(A + (size_t)(rowBase + aRow) * D + k0 + aCol4);
        As[aCol4 + 0][aRow] = av.x;
        As[aCol4 + 1][aRow] = av.y;
        As[aCol4 + 2][aRow] = av.z;
        As[aCol4 + 3][aRow] = av.w;
        *reinterpret_cast<float4*>(&Bs[bRow][bCol4]) =
            *reinterpret_cast<const float4*>(W + (size_t)(k0 + bRow) * HD + colBase + bCol4);
        __syncthreads();

        #pragma unroll
        for (int k = 0; k < BK; k++) {
            float a[TM], b[TN];
            *reinterpret_cast<float4*>(&a[0]) = *reinterpret_cast<const float4*>(&As[k][ty * TM]);
            *reinterpret_cast<float4*>(&a[4]) = *reinterpret_cast<const float4*>(&As[k][ty * TM + 4]);
            *reinterpret_cast<float4*>(&b[0]) = *reinterpret_cast<const float4*>(&Bs[k][tx * TN]);
            *reinterpret_cast<float4*>(&b[4]) = *reinterpret_cast<const float4*>(&Bs[k][tx * TN + 4]);
            #pragma unroll
            for (int i = 0; i < TM; i++)
                #pragma unroll
                for (int j = 0; j < TN; j++)
                    acc[i][j] += a[i] * b[j];
        }
        __syncthreads();
    }
}

// QKV projection: z in {0,1,2} selects Wq/Wk/Wv -> g_Q/g_K/g_V in [bh][n][d] layout
__global__ __launch_bounds__(256, 2)
void qkv_gemm(const float* __restrict__ X,
              const float* __restrict__ Wq,
              const float* __restrict__ Wk,
              const float* __restrict__ Wv) {
    const float* W = (blockIdx.z == 0) ? Wq : (blockIdx.z == 1) ? Wk : Wv;
    float* Out     = (blockIdx.z == 0) ? g_Q : (blockIdx.z == 1) ? g_K : g_V;

    const int rowBase = blockIdx.y * BM;
    const int colBase = blockIdx.x * BN;
    float acc[TM][TN] = {};
    sgemm_body(X, W, acc, rowBase, colBase);

    const int tx = threadIdx.x & 15;
    const int ty = threadIdx.x >> 4;
    #pragma unroll
    for (int i = 0; i < TM; i++) {
        const int r = rowBase + ty * TM + i;
        const int b = r >> 11;          // /N
        const int n = r & (N - 1);
        #pragma unroll
        for (int j = 0; j < TN; j++) {
            const int c = colBase + tx * TN + j;
            const int h = c >> 6;
            const int d = c & 63;
            Out[(((size_t)(b * H + h)) * N + n) * DK + d] = acc[i][j];
        }
    }
}

// Output projection: g_att [8192,1024] @ Wo -> out (row-major)
__global__ __launch_bounds__(256, 2)
void out_gemm(const float* __restrict__ Wo, float* __restrict__ Cout) {
    const int rowBase = blockIdx.y * BM;
    const int colBase = blockIdx.x * BN;
    float acc[TM][TN] = {};
    sgemm_body(g_att, Wo, acc, rowBase, colBase);

    const int tx = threadIdx.x & 15;
    const int ty = threadIdx.x >> 4;
    #pragma unroll
    for (int i = 0; i < TM; i++) {
        const int r = rowBase + ty * TM + i;
        #pragma unroll
        for (int j = 0; j < TN; j++) {
            const int c = colBase + tx * TN + j;
            Cout[(size_t)r * HD + c] = acc[i][j];
        }
    }
}

// ---------------------------------------------------------------------------
// Flash-attention (fp32, causal). One block = 64 query rows x one (b,h).
// 256 threads (16x16), each thread owns a 4x4 register tile.
// ---------------------------------------------------------------------------
constexpr int TQ = 64;                       // query tile
constexpr int PAD = 65;                      // smem row pitch
constexpr int ATT_SMEM = 4 * 64 * PAD * (int)sizeof(float);  // 66560 B

__global__ __launch_bounds__(256)
void flash_attn() {
    extern __shared__ float sm[];
    float* QsT = sm;                  // [64(k)][65]: QsT[d][r], pre-scaled
    float* KsT = QsT + 64 * PAD;      // KsT[d][c]
    float* Vs  = KsT + 64 * PAD;      // Vs[k][d]
    float* PsT = Vs  + 64 * PAD;      // PsT[c][r]

    const int bh = blockIdx.y;                // b*H + h
    const int qt = blockIdx.x;
    const int q0 = qt * TQ;
    const int b  = bh >> 4;
    const int h  = bh & (H - 1);

    const float* Qg = g_Q + (size_t)bh * N * DK;
    const float* Kg = g_K + (size_t)bh * N * DK;
    const float* Vg = g_V + (size_t)bh * N * DK;

    const int tid = threadIdx.x;
    const int tx = tid & 15;
    const int ty = tid >> 4;

    // Load Q tile (scaled by 1/sqrt(DK) = 0.125), transposed
    for (int i = tid; i < 64 * 64; i += 256) {
        const int r = i >> 6, d = i & 63;
        QsT[d * PAD + r] = Qg[(size_t)(q0 + r) * DK + d] * 0.125f;
    }

    float m[4], l[4], o[4][4];
    #pragma unroll
    for (int i = 0; i < 4; i++) {
        m[i] = -1e30f; l[i] = 0.f;
        #pragma unroll
        for (int j = 0; j < 4; j++) o[i][j] = 0.f;
    }

    for (int jt = 0; jt <= qt; jt++) {
        const int j0 = jt * 64;
        __syncthreads();   // protect KsT/Vs/PsT from previous iteration readers
        for (int i = tid; i < 64 * 64; i += 256) {
            const int r = i >> 6, d = i & 63;
            const float kv = Kg[(size_t)(j0 + r) * DK + d];
            const float vv = Vg[(size_t)(j0 + r) * DK + d];
            KsT[d * PAD + r] = kv;
            Vs[r * PAD + d]  = vv;
        }
        __syncthreads();

        // S = (Q*scale) @ K^T   (4x4 per thread)
        float s[4][4] = {};
        #pragma unroll 4
        for (int k = 0; k < 64; k++) {
            float qv[4], kv[4];
            #pragma unroll
            for (int i = 0; i < 4; i++) qv[i] = QsT[k * PAD + ty * 4 + i];
            #pragma unroll
            for (int j = 0; j < 4; j++) kv[j] = KsT[k * PAD + tx * 4 + j];
            #pragma unroll
            for (int i = 0; i < 4; i++)
                #pragma unroll
                for (int j = 0; j < 4; j++) s[i][j] += qv[i] * kv[j];
        }

        // causal mask (only the diagonal tile needs it)
        if (jt == qt) {
            #pragma unroll
            for (int i = 0; i < 4; i++)
                #pragma unroll
                for (int j = 0; j < 4; j++)
                    if (j0 + tx * 4 + j > q0 + ty * 4 + i) s[i][j] = -1e30f;
        }

        // online softmax update
        float alpha[4];
        #pragma unroll
        for (int i = 0; i < 4; i++) {
            float rm = fmaxf(fmaxf(s[i][0], s[i][1]), fmaxf(s[i][2], s[i][3]));
            #pragma unroll
            for (int off = 8; off >= 1; off >>= 1)
                rm = fmaxf(rm, __shfl_xor_sync(0xffffffffu, rm, off, 16));
            const float mnew = fmaxf(m[i], rm);
            alpha[i] = __expf(m[i] - mnew);
            m[i] = mnew;

            float rs = 0.f;
            #pragma unroll
            for (int j = 0; j < 4; j++) {
                s[i][j] = __expf(s[i][j] - mnew);
                rs += s[i][j];
            }
            #pragma unroll
            for (int off = 8; off >= 1; off >>= 1)
                rs += __shfl_xor_sync(0xffffffffu, rs, off, 16);
            l[i] = l[i] * alpha[i] + rs;
        }

        // stage P (transposed) for the O GEMM
        #pragma unroll
        for (int i = 0; i < 4; i++)
            #pragma unroll
            for (int j = 0; j < 4; j++)
                PsT[(tx * 4 + j) * PAD + (ty * 4 + i)] = s[i][j];
        __syncthreads();

        // O = O*alpha + P @ V
        #pragma unroll
        for (int i = 0; i < 4; i++)
            #pragma unroll
            for (int j = 0; j < 4; j++)
                o[i][j] *= alpha[i];

        #pragma unroll 4
        for (int k = 0; k < 64; k++) {
            float pv[4], vv[4];
            #pragma unroll
            for (int i = 0; i < 4; i++) pv[i] = PsT[k * PAD + ty * 4 + i];
            #pragma unroll
            for (int j = 0; j < 4; j++) vv[j] = Vs[k * PAD + tx * 4 + j];
            #pragma unroll
            for (int i = 0; i < 4; i++)
                #pragma unroll
                for (int j = 0; j < 4; j++)
                    o[i][j] += pv[i] * vv[j];
        }
    }

    // epilogue: normalize and write to [b][n][h*DK]
    #pragma unroll
    for (int i = 0; i < 4; i++) {
        const float inv = 1.0f / l[i];
        const int r = q0 + ty * 4 + i;
        #pragma unroll
        for (int j = 0; j < 4; j++) {
            const int c = h * DK + tx * 4 + j;
            g_att[((size_t)b * N + r) * HD + c] = o[i][j] * inv;
        }
    }
}

// ---------------------------------------------------------------------------
extern "C" void kernel_launch(void* const* d_in, const int* in_sizes, int n_in,
                              void* d_out, int out_size) {
    const float* X  = (const float*)d_in[0];
    // d_in[1] = mask (pure causal -> applied analytically)
    const float* Wq = (const float*)d_in[2];
    const float* Wk = (const float*)d_in[3];
    const float* Wv = (const float*)d_in[4];
    const float* Wo = (const float*)d_in[5];
    float* out = (float*)d_out;

    // 1) QKV projections (3 GEMMs in one grid)
    dim3 gproj(HD / BN, (B * N) / BM, 3);     // (8, 64, 3)
    qkv_gemm<<<gproj, 256>>>(X, Wq, Wk, Wv);

    // 2) causal flash attention
    cudaFuncSetAttribute(flash_attn, cudaFuncAttributeMaxDynamicSharedMemorySize, ATT_SMEM);
    dim3 gatt(N / TQ, B * H);                  // (32, 64)
    flash_attn<<<gatt, 256, ATT_SMEM>>>();

    // 3) output projection
    dim3 gout(HD / BN, (B * N) / BM);          // (8, 64)
    out_gemm<<<gout, 256>>>(Wo, out);
}

// round 6
// speedup vs baseline: 1.4335x; 1.4335x over previous
#include <cuda_runtime.h>
#include <cuda_bf16.h>
#include <cstdint>
#include <math.h>

// Problem constants
constexpr int B  = 4;
constexpr int N  = 2048;
constexpr int D  = 1024;
constexpr int H  = 16;
constexpr int DK = 64;
constexpr int HD = H * DK;   // 1024

// ---------------------------------------------------------------------------
// Scratch (device globals — no allocation allowed)
// ---------------------------------------------------------------------------
__device__ float g_Q[(size_t)B * H * N * DK];    // [bh][n][d] fp32
__device__ float g_K[(size_t)B * H * N * DK];
__device__ float g_V[(size_t)B * H * N * DK];
__device__ __nv_bfloat16 g_Xhi[(size_t)B * N * D];   // X split, [m][k]
__device__ __nv_bfloat16 g_Xlo[(size_t)B * N * D];
__device__ __nv_bfloat16 g_WThi[4][(size_t)D * HD];  // W^T split, [n][k] (0=q,1=k,2=v,3=o)
__device__ __nv_bfloat16 g_WTlo[4][(size_t)D * HD];
__device__ __nv_bfloat16 g_AThi[(size_t)B * N * HD]; // attention out split, [m][k]
__device__ __nv_bfloat16 g_ATlo[(size_t)B * N * HD];

// ---------------------------------------------------------------------------
// PTX helpers (generic sm_80+ path — NO 'a'-suffix features; the harness PTX
// stage targets compute_103 which rejects tcgen05/TMA-tensor instructions)
// ---------------------------------------------------------------------------
__device__ __forceinline__ uint32_t smem_u32(const void* p) {
    uint32_t a;
    asm("{ .reg .u64 t; cvta.to.shared.u64 t, %1; cvt.u32.u64 %0, t; }" : "=r"(a) : "l"(p));
    return a;
}
__device__ __forceinline__ void cp16(uint32_t dst, const void* src) {
    asm volatile("cp.async.cg.shared.global [%0], [%1], 16;" :: "r"(dst), "l"(src));
}
__device__ __forceinline__ void ldsm4(uint32_t& r0, uint32_t& r1, uint32_t& r2, uint32_t& r3,
                                      uint32_t addr) {
    asm volatile("ldmatrix.sync.aligned.m8n8.x4.shared.b16 {%0,%1,%2,%3}, [%4];"
                 : "=r"(r0), "=r"(r1), "=r"(r2), "=r"(r3) : "r"(addr));
}
__device__ __forceinline__ void mma16816(float* c,
                                         uint32_t a0, uint32_t a1, uint32_t a2, uint32_t a3,
                                         uint32_t b0, uint32_t b1) {
    asm volatile("mma.sync.aligned.m16n8k16.row.col.f32.bf16.bf16.f32 "
                 "{%0,%1,%2,%3}, {%4,%5,%6,%7}, {%8,%9}, {%0,%1,%2,%3};"
                 : "+f"(c[0]), "+f"(c[1]), "+f"(c[2]), "+f"(c[3])
                 : "r"(a0), "r"(a1), "r"(a2), "r"(a3), "r"(b0), "r"(b1));
}

// ---------------------------------------------------------------------------
// bf16-split HMMA GEMM: C[128,128] = A[128,1024] @ B[1024,128], B given as
// B^T [n][k] K-major. 3 products: Ah*Bh + Ah*Bl + Al*Bh (fp32 accumulate).
// 8 warps (2m x 4n), warp tile 64x32. K chunks of 32, cp.async double buffer.
// ---------------------------------------------------------------------------
constexpr int APITCH_B = 80;                     // smem row pitch bytes (64B data + 16B pad)
constexpr int ARR_B    = 128 * APITCH_B;         // one operand array: 10240 B
constexpr int STAGE_B  = 4 * ARR_B;              // Ahi|Alo|Bhi|Blo: 40960 B
constexpr int GSMEM    = 2 * STAGE_B;            // 81920 B

__device__ __forceinline__ void gemm_mma_body(
    const __nv_bfloat16* __restrict__ Ahi, const __nv_bfloat16* __restrict__ Alo,
    const __nv_bfloat16* __restrict__ Bhi, const __nv_bfloat16* __restrict__ Blo,
    int rowBase, int colBase, char* sm, float acc[4][4][4])
{
    const int tid  = threadIdx.x;
    const int lane = tid & 31;
    const int w    = tid >> 5;
    const int wm   = (w >> 2) * 64;   // warp m offset within CTA tile
    const int wn   = (w & 3) * 32;    // warp n offset
    const uint32_t sb = smem_u32(sm);

    auto load_stage = [&](int s, int k0) {
        const uint32_t base = sb + s * STAGE_B;
        #pragma unroll
        for (int a = 0; a < 4; ++a) {
            const __nv_bfloat16* src = (a == 0) ? Ahi : (a == 1) ? Alo : (a == 2) ? Bhi : Blo;
            const int rb = (a < 2) ? rowBase : colBase;
            #pragma unroll
            for (int t = 0; t < 2; ++t) {
                const int idx = tid * 2 + t;        // 0..511
                const int r = idx >> 2, ch = idx & 3;
                cp16(base + a * ARR_B + r * APITCH_B + ch * 16,
                     src + (size_t)(rb + r) * D + k0 + ch * 8);
            }
        }
    };

    auto comp = [&](int s) {
        const uint32_t base = sb + s * STAGE_B;
        #pragma unroll
        for (int k16 = 0; k16 < 2; ++k16) {
            uint32_t Ah[4][4], Al[4][4], Bh[2][4], Bl[2][4];
            #pragma unroll
            for (int mi = 0; mi < 4; ++mi) {
                const uint32_t addr = base + (wm + mi * 16 + (lane & 15)) * APITCH_B
                                      + k16 * 32 + (lane >> 4) * 16;
                ldsm4(Ah[mi][0], Ah[mi][1], Ah[mi][2], Ah[mi][3], addr);
                ldsm4(Al[mi][0], Al[mi][1], Al[mi][2], Al[mi][3], addr + ARR_B);
            }
            #pragma unroll
            for (int np = 0; np < 2; ++np) {
                const int nrow = wn + np * 16 + (lane & 7) + ((lane >> 4) << 3);
                const uint32_t addr = base + 2 * ARR_B + nrow * APITCH_B
                                      + k16 * 32 + ((lane >> 3) & 1) * 16;
                ldsm4(Bh[np][0], Bh[np][1], Bh[np][2], Bh[np][3], addr);
                ldsm4(Bl[np][0], Bl[np][1], Bl[np][2], Bl[np][3], addr + ARR_B);
            }
            #pragma unroll
            for (int mi = 0; mi < 4; ++mi)
                #pragma unroll
                for (int nf = 0; nf < 4; ++nf) {
                    const int np = nf >> 1, hh = (nf & 1) * 2;
                    mma16816(acc[mi][nf], Ah[mi][0], Ah[mi][1], Ah[mi][2], Ah[mi][3],
                             Bh[np][hh], Bh[np][hh + 1]);
                    mma16816(acc[mi][nf], Ah[mi][0], Ah[mi][1], Ah[mi][2], Ah[mi][3],
                             Bl[np][hh], Bl[np][hh + 1]);
                    mma16816(acc[mi][nf], Al[mi][0], Al[mi][1], Al[mi][2], Al[mi][3],
                             Bh[np][hh], Bh[np][hh + 1]);
                }
        }
    };

    constexpr int NC = D / 32;   // 32 chunks
    load_stage(0, 0);
    asm volatile("cp.async.commit_group;" ::: "memory");
    for (int c = 0; c < NC; ++c) {
        if (c + 1 < NC) load_stage((c + 1) & 1, (c + 1) * 32);
        asm volatile("cp.async.commit_group;" ::: "memory");
        asm volatile("cp.async.wait_group 1;" ::: "memory");
        __syncthreads();
        comp(c & 1);
        __syncthreads();
    }
}

// QKV projection: z selects Wq/Wk/Wv; scatter into per-head [bh][n][d] fp32
__global__ __launch_bounds__(256, 1) void qkv_mma() {
    extern __shared__ char sm[];
    const int z = blockIdx.z;
    const int rowBase = blockIdx.y * 128, colBase = blockIdx.x * 128;
    float acc[4][4][4];
    #pragma unroll
    for (int i = 0; i < 4; ++i)
        #pragma unroll
        for (int j = 0; j < 4; ++j)
            #pragma unroll
            for (int k = 0; k < 4; ++k) acc[i][j][k] = 0.f;

    gemm_mma_body(g_Xhi, g_Xlo, g_WThi[z], g_WTlo[z], rowBase, colBase, sm, acc);

    float* Out = (z == 0) ? g_Q : (z == 1) ? g_K : g_V;
    const int lane = threadIdx.x & 31, w = threadIdx.x >> 5;
    const int wm = (w >> 2) * 64, wn = (w & 3) * 32;
    #pragma unroll
    for (int mi = 0; mi < 4; ++mi)
        #pragma unroll
        for (int nf = 0; nf < 4; ++nf) {
            const int r0 = rowBase + wm + mi * 16 + (lane >> 2);
            const int c0 = colBase + wn + nf * 8 + (lane & 3) * 2;
            #pragma unroll
            for (int e = 0; e < 4; ++e) {
                const int r = r0 + (e >> 1) * 8;
                const int c = c0 + (e & 1);
                const int b = r >> 11, n = r & (N - 1);
                const int h = c >> 6, dd = c & 63;
                Out[(((size_t)(b * H + h)) * N + n) * DK + dd] = acc[mi][nf][e];
            }
        }
}

// Output projection: attention-out (split) @ Wo -> d_out fp32
__global__ __launch_bounds__(256, 1) void out_mma(float* __restrict__ Cout) {
    extern __shared__ char sm[];
    const int rowBase = blockIdx.y * 128, colBase = blockIdx.x * 128;
    float acc[4][4][4];
    #pragma unroll
    for (int i = 0; i < 4; ++i)
        #pragma unroll
        for (int j = 0; j < 4; ++j)
            #pragma unroll
            for (int k = 0; k < 4; ++k) acc[i][j][k] = 0.f;

    gemm_mma_body(g_AThi, g_ATlo, g_WThi[3], g_WTlo[3], rowBase, colBase, sm, acc);

    const int lane = threadIdx.x & 31, w = threadIdx.x >> 5;
    const int wm = (w >> 2) * 64, wn = (w & 3) * 32;
    #pragma unroll
    for (int mi = 0; mi < 4; ++mi)
        #pragma unroll
        for (int nf = 0; nf < 4; ++nf) {
            const int r0 = rowBase + wm + mi * 16 + (lane >> 2);
            const int c0 = colBase + wn + nf * 8 + (lane & 3) * 2;
            #pragma unroll
            for (int e = 0; e < 4; ++e)
                Cout[(size_t)(r0 + (e >> 1) * 8) * HD + c0 + (e & 1)] = acc[mi][nf][e];
        }
}

// ---------------------------------------------------------------------------
// Precision-split conversion passes
// ---------------------------------------------------------------------------
__global__ void convX(const float* __restrict__ X) {
    const size_t i = ((size_t)blockIdx.x * 256 + threadIdx.x) * 2;
    const float2 v = *(const float2*)(X + i);
    const __nv_bfloat16 h0 = __float2bfloat16(v.x);
    const __nv_bfloat16 h1 = __float2bfloat16(v.y);
    __nv_bfloat162 hp; hp.x = h0; hp.y = h1;
    __nv_bfloat162 lp;
    lp.x = __float2bfloat16(v.x - __bfloat162float(h0));
    lp.y = __float2bfloat16(v.y - __bfloat162float(h1));
    *(__nv_bfloat162*)(g_Xhi + i) = hp;
    *(__nv_bfloat162*)(g_Xlo + i) = lp;
}

// Transpose+split: WT[n][k] = W[k][n] for Wq/Wk/Wv/Wo (z = 0..3)
__global__ void convW(const float* __restrict__ Wq, const float* __restrict__ Wk,
                      const float* __restrict__ Wv, const float* __restrict__ Wo) {
    const int z = blockIdx.z;
    const float* W = (z == 0) ? Wq : (z == 1) ? Wk : (z == 2) ? Wv : Wo;
    __nv_bfloat16* Th = g_WThi[z];
    __nv_bfloat16* Tl = g_WTlo[z];
    __shared__ float t[32][33];
    const int k0 = blockIdx.x * 32, n0 = blockIdx.y * 32;
    #pragma unroll
    for (int j = 0; j < 32; j += 8)
        t[threadIdx.y + j][threadIdx.x] = W[(size_t)(k0 + threadIdx.y + j) * HD + n0 + threadIdx.x];
    __syncthreads();
    #pragma unroll
    for (int j = 0; j < 32; j += 8) {
        const int n = n0 + threadIdx.y + j, k = k0 + threadIdx.x;
        const float v = t[threadIdx.x][threadIdx.y + j];
        const __nv_bfloat16 h = __float2bfloat16(v);
        Th[(size_t)n * D + k] = h;
        Tl[(size_t)n * D + k] = __float2bfloat16(v - __bfloat162float(h));
    }
}

// ---------------------------------------------------------------------------
// Flash-attention (fp32, causal) — proven correct; epilogue emits bf16 hi/lo
// ---------------------------------------------------------------------------
constexpr int TQ = 64;
constexpr int PAD = 65;
constexpr int ATT_SMEM = 4 * 64 * PAD * (int)sizeof(float);

__global__ __launch_bounds__(256)
void flash_attn() {
    extern __shared__ float smf[];
    float* QsT = smf;
    float* KsT = QsT + 64 * PAD;
    float* Vs  = KsT + 64 * PAD;
    float* PsT = Vs  + 64 * PAD;

    const int bh = blockIdx.y;
    const int qt = blockIdx.x;
    const int q0 = qt * TQ;
    const int b  = bh >> 4;
    const int h  = bh & (H - 1);

    const float* Qg = g_Q + (size_t)bh * N * DK;
    const float* Kg = g_K + (size_t)bh * N * DK;
    const float* Vg = g_V + (size_t)bh * N * DK;

    const int tid = threadIdx.x;
    const int tx = tid & 15;
    const int ty = tid >> 4;

    for (int i = tid; i < 64 * 64; i += 256) {
        const int r = i >> 6, d = i & 63;
        QsT[d * PAD + r] = Qg[(size_t)(q0 + r) * DK + d] * 0.125f;
    }

    float m[4], l[4], o[4][4];
    #pragma unroll
    for (int i = 0; i < 4; i++) {
        m[i] = -1e30f; l[i] = 0.f;
        #pragma unroll
        for (int j = 0; j < 4; j++) o[i][j] = 0.f;
    }

    for (int jt = 0; jt <= qt; jt++) {
        const int j0 = jt * 64;
        __syncthreads();
        for (int i = tid; i < 64 * 64; i += 256) {
            const int r = i >> 6, d = i & 63;
            KsT[d * PAD + r] = Kg[(size_t)(j0 + r) * DK + d];
            Vs[r * PAD + d]  = Vg[(size_t)(j0 + r) * DK + d];
        }
        __syncthreads();

        float s[4][4] = {};
        #pragma unroll 4
        for (int k = 0; k < 64; k++) {
            float qv[4], kv[4];
            #pragma unroll
            for (int i = 0; i < 4; i++) qv[i] = QsT[k * PAD + ty * 4 + i];
            #pragma unroll
            for (int j = 0; j < 4; j++) kv[j] = KsT[k * PAD + tx * 4 + j];
            #pragma unroll
            for (int i = 0; i < 4; i++)
                #pragma unroll
                for (int j = 0; j < 4; j++) s[i][j] += qv[i] * kv[j];
        }

        if (jt == qt) {
            #pragma unroll
            for (int i = 0; i < 4; i++)
                #pragma unroll
                for (int j = 0; j < 4; j++)
                    if (j0 + tx * 4 + j > q0 + ty * 4 + i) s[i][j] = -1e30f;
        }

        float alpha[4];
        #pragma unroll
        for (int i = 0; i < 4; i++) {
            float rm = fmaxf(fmaxf(s[i][0], s[i][1]), fmaxf(s[i][2], s[i][3]));
            #pragma unroll
            for (int off = 8; off >= 1; off >>= 1)
                rm = fmaxf(rm, __shfl_xor_sync(0xffffffffu, rm, off, 16));
            const float mnew = fmaxf(m[i], rm);
            alpha[i] = __expf(m[i] - mnew);
            m[i] = mnew;

            float rs = 0.f;
            #pragma unroll
            for (int j = 0; j < 4; j++) {
                s[i][j] = __expf(s[i][j] - mnew);
                rs += s[i][j];
            }
            #pragma unroll
            for (int off = 8; off >= 1; off >>= 1)
                rs += __shfl_xor_sync(0xffffffffu, rs, off, 16);
            l[i] = l[i] * alpha[i] + rs;
        }

        #pragma unroll
        for (int i = 0; i < 4; i++)
            #pragma unroll
            for (int j = 0; j < 4; j++)
                PsT[(tx * 4 + j) * PAD + (ty * 4 + i)] = s[i][j];
        __syncthreads();

        #pragma unroll
        for (int i = 0; i < 4; i++)
            #pragma unroll
            for (int j = 0; j < 4; j++)
                o[i][j] *= alpha[i];

        #pragma unroll 4
        for (int k = 0; k < 64; k++) {
            float pv[4], vv[4];
            #pragma unroll
            for (int i = 0; i < 4; i++) pv[i] = PsT[k * PAD + ty * 4 + i];
            #pragma unroll
            for (int j = 0; j < 4; j++) vv[j] = Vs[k * PAD + tx * 4 + j];
            #pragma unroll
            for (int i = 0; i < 4; i++)
                #pragma unroll
                for (int j = 0; j < 4; j++)
                    o[i][j] += pv[i] * vv[j];
        }
    }

    // epilogue: normalize, split to bf16 hi/lo for the output projection
    #pragma unroll
    for (int i = 0; i < 4; i++) {
        const float inv = 1.0f / l[i];
        const int r = q0 + ty * 4 + i;
        #pragma unroll
        for (int j = 0; j < 4; j++) {
            const int c = h * DK + tx * 4 + j;
            const float v = o[i][j] * inv;
            const __nv_bfloat16 hi = __float2bfloat16(v);
            const size_t idx = ((size_t)b * N + r) * HD + c;
            g_AThi[idx] = hi;
            g_ATlo[idx] = __float2bfloat16(v - __bfloat162float(hi));
        }
    }
}

// ---------------------------------------------------------------------------
extern "C" void kernel_launch(void* const* d_in, const int* in_sizes, int n_in,
                              void* d_out, int out_size) {
    const float* X  = (const float*)d_in[0];
    // d_in[1] = mask (pure causal -> applied analytically)
    const float* Wq = (const float*)d_in[2];
    const float* Wk = (const float*)d_in[3];
    const float* Wv = (const float*)d_in[4];
    const float* Wo = (const float*)d_in[5];
    float* out = (float*)d_out;

    cudaFuncSetAttribute(qkv_mma, cudaFuncAttributeMaxDynamicSharedMemorySize, GSMEM);
    cudaFuncSetAttribute(out_mma, cudaFuncAttributeMaxDynamicSharedMemorySize, GSMEM);
    cudaFuncSetAttribute(flash_attn, cudaFuncAttributeMaxDynamicSharedMemorySize, ATT_SMEM);

    // 0) precision-split conversions
    convX<<<(B * N * D / 2) / 256, 256>>>(X);
    convW<<<dim3(D / 32, HD / 32, 4), dim3(32, 8)>>>(Wq, Wk, Wv, Wo);

    // 1) QKV projections on tensor cores (legacy HMMA path)
    qkv_mma<<<dim3(HD / 128, (B * N) / 128, 3), 256, GSMEM>>>();   // (8, 64, 3)

    // 2) causal flash attention (fp32)
    flash_attn<<<dim3(N / TQ, B * H), 256, ATT_SMEM>>>();          // (32, 64)

    // 3) output projection on tensor cores
    out_mma<<<dim3(HD / 128, (B * N) / 128), 256, GSMEM>>>(out);   // (8, 64)
}

// round 7
// speedup vs baseline: 1.7187x; 1.1989x over previous
#include <cuda_runtime.h>
#include <cuda_bf16.h>
#include <cstdint>
#include <math.h>

// Problem constants
constexpr int B  = 4;
constexpr int N  = 2048;
constexpr int D  = 1024;
constexpr int H  = 16;
constexpr int DK = 64;
constexpr int HD = H * DK;   // 1024

// ---------------------------------------------------------------------------
// Scratch (device globals — no allocation allowed)
// ---------------------------------------------------------------------------
__device__ __nv_bfloat16 g_Qhi[(size_t)B * H * N * DK];  // [bh][n][dk], pre-scaled 0.125
__device__ __nv_bfloat16 g_Qlo[(size_t)B * H * N * DK];
__device__ __nv_bfloat16 g_Khi[(size_t)B * H * N * DK];
__device__ __nv_bfloat16 g_Klo[(size_t)B * H * N * DK];
__device__ __nv_bfloat16 g_Vhi[(size_t)B * H * N * DK];
__device__ __nv_bfloat16 g_Vlo[(size_t)B * H * N * DK];
__device__ __nv_bfloat16 g_Xhi[(size_t)B * N * D];       // X split, [m][k]
__device__ __nv_bfloat16 g_Xlo[(size_t)B * N * D];
__device__ __nv_bfloat16 g_WThi[4][(size_t)D * HD];      // W^T split, [n][k] (0=q,1=k,2=v,3=o)
__device__ __nv_bfloat16 g_WTlo[4][(size_t)D * HD];
__device__ __nv_bfloat16 g_AThi[(size_t)B * N * HD];     // attention out split, [m][k]
__device__ __nv_bfloat16 g_ATlo[(size_t)B * N * HD];

// ---------------------------------------------------------------------------
// PTX helpers (generic sm_80+ path — harness PTX targets compute_103, which
// rejects tcgen05/'a'-suffix features; legacy HMMA/ldmatrix/cp.async only)
// ---------------------------------------------------------------------------
__device__ __forceinline__ uint32_t smem_u32(const void* p) {
    uint32_t a;
    asm("{ .reg .u64 t; cvta.to.shared.u64 t, %1; cvt.u32.u64 %0, t; }" : "=r"(a) : "l"(p));
    return a;
}
__device__ __forceinline__ void cp16(uint32_t dst, const void* src) {
    asm volatile("cp.async.cg.shared.global [%0], [%1], 16;" :: "r"(dst), "l"(src));
}
__device__ __forceinline__ void ldsm4(uint32_t& r0, uint32_t& r1, uint32_t& r2, uint32_t& r3,
                                      uint32_t addr) {
    asm volatile("ldmatrix.sync.aligned.m8n8.x4.shared.b16 {%0,%1,%2,%3}, [%4];"
                 : "=r"(r0), "=r"(r1), "=r"(r2), "=r"(r3) : "r"(addr));
}
__device__ __forceinline__ void ldsm4t(uint32_t& r0, uint32_t& r1, uint32_t& r2, uint32_t& r3,
                                       uint32_t addr) {
    asm volatile("ldmatrix.sync.aligned.m8n8.x4.trans.shared.b16 {%0,%1,%2,%3}, [%4];"
                 : "=r"(r0), "=r"(r1), "=r"(r2), "=r"(r3) : "r"(addr));
}
__device__ __forceinline__ void mma16816(float* c,
                                         uint32_t a0, uint32_t a1, uint32_t a2, uint32_t a3,
                                         uint32_t b0, uint32_t b1) {
    asm volatile("mma.sync.aligned.m16n8k16.row.col.f32.bf16.bf16.f32 "
                 "{%0,%1,%2,%3}, {%4,%5,%6,%7}, {%8,%9}, {%0,%1,%2,%3};"
                 : "+f"(c[0]), "+f"(c[1]), "+f"(c[2]), "+f"(c[3])
                 : "r"(a0), "r"(a1), "r"(a2), "r"(a3), "r"(b0), "r"(b1));
}
// split v0,v1 into packed bf16 hi pair (return) and lo pair (out param)
__device__ __forceinline__ uint32_t packsplit(float v0, float v1, uint32_t& lo) {
    const __nv_bfloat16 h0 = __float2bfloat16(v0);
    const __nv_bfloat16 h1 = __float2bfloat16(v1);
    __nv_bfloat162 hp; hp.x = h0; hp.y = h1;
    __nv_bfloat162 lp;
    lp.x = __float2bfloat16(v0 - __bfloat162float(h0));
    lp.y = __float2bfloat16(v1 - __bfloat162float(h1));
    lo = *reinterpret_cast<uint32_t*>(&lp);
    return *reinterpret_cast<uint32_t*>(&hp);
}

// ---------------------------------------------------------------------------
// bf16-split HMMA GEMM body (verified round 6): C[128,128] = A[128,1024]@B,
// B given as B^T [n][k]. 3 products Ah*Bh + Ah*Bl + Al*Bh, fp32 accumulate.
// ---------------------------------------------------------------------------
constexpr int APITCH_B = 80;
constexpr int ARR_B    = 128 * APITCH_B;
constexpr int STAGE_B  = 4 * ARR_B;
constexpr int GSMEM    = 2 * STAGE_B;

__device__ __forceinline__ void gemm_mma_body(
    const __nv_bfloat16* __restrict__ Ahi, const __nv_bfloat16* __restrict__ Alo,
    const __nv_bfloat16* __restrict__ Bhi, const __nv_bfloat16* __restrict__ Blo,
    int rowBase, int colBase, char* sm, float acc[4][4][4])
{
    const int tid  = threadIdx.x;
    const int lane = tid & 31;
    const int w    = tid >> 5;
    const int wm   = (w >> 2) * 64;
    const int wn   = (w & 3) * 32;
    const uint32_t sb = smem_u32(sm);

    auto load_stage = [&](int s, int k0) {
        const uint32_t base = sb + s * STAGE_B;
        #pragma unroll
        for (int a = 0; a < 4; ++a) {
            const __nv_bfloat16* src = (a == 0) ? Ahi : (a == 1) ? Alo : (a == 2) ? Bhi : Blo;
            const int rb = (a < 2) ? rowBase : colBase;
            #pragma unroll
            for (int t = 0; t < 2; ++t) {
                const int idx = tid * 2 + t;
                const int r = idx >> 2, ch = idx & 3;
                cp16(base + a * ARR_B + r * APITCH_B + ch * 16,
                     src + (size_t)(rb + r) * D + k0 + ch * 8);
            }
        }
    };

    auto comp = [&](int s) {
        const uint32_t base = sb + s * STAGE_B;
        #pragma unroll
        for (int k16 = 0; k16 < 2; ++k16) {
            uint32_t Ah[4][4], Al[4][4], Bh[2][4], Bl[2][4];
            #pragma unroll
            for (int mi = 0; mi < 4; ++mi) {
                const uint32_t addr = base + (wm + mi * 16 + (lane & 15)) * APITCH_B
                                      + k16 * 32 + (lane >> 4) * 16;
                ldsm4(Ah[mi][0], Ah[mi][1], Ah[mi][2], Ah[mi][3], addr);
                ldsm4(Al[mi][0], Al[mi][1], Al[mi][2], Al[mi][3], addr + ARR_B);
            }
            #pragma unroll
            for (int np = 0; np < 2; ++np) {
                const int nrow = wn + np * 16 + (lane & 7) + ((lane >> 4) << 3);
                const uint32_t addr = base + 2 * ARR_B + nrow * APITCH_B
                                      + k16 * 32 + ((lane >> 3) & 1) * 16;
                ldsm4(Bh[np][0], Bh[np][1], Bh[np][2], Bh[np][3], addr);
                ldsm4(Bl[np][0], Bl[np][1], Bl[np][2], Bl[np][3], addr + ARR_B);
            }
            #pragma unroll
            for (int mi = 0; mi < 4; ++mi)
                #pragma unroll
                for (int nf = 0; nf < 4; ++nf) {
                    const int np = nf >> 1, hh = (nf & 1) * 2;
                    mma16816(acc[mi][nf], Ah[mi][0], Ah[mi][1], Ah[mi][2], Ah[mi][3],
                             Bh[np][hh], Bh[np][hh + 1]);
                    mma16816(acc[mi][nf], Ah[mi][0], Ah[mi][1], Ah[mi][2], Ah[mi][3],
                             Bl[np][hh], Bl[np][hh + 1]);
                    mma16816(acc[mi][nf], Al[mi][0], Al[mi][1], Al[mi][2], Al[mi][3],
                             Bh[np][hh], Bh[np][hh + 1]);
                }
        }
    };

    constexpr int NC = D / 32;
    load_stage(0, 0);
    asm volatile("cp.async.commit_group;" ::: "memory");
    for (int c = 0; c < NC; ++c) {
        if (c + 1 < NC) load_stage((c + 1) & 1, (c + 1) * 32);
        asm volatile("cp.async.commit_group;" ::: "memory");
        asm volatile("cp.async.wait_group 1;" ::: "memory");
        __syncthreads();
        comp(c & 1);
        __syncthreads();
    }
}

// QKV projection: epilogue writes bf16 hi/lo per-head tensors (Q pre-scaled)
__global__ __launch_bounds__(256, 1) void qkv_mma() {
    extern __shared__ char sm[];
    const int z = blockIdx.z;
    const int rowBase = blockIdx.y * 128, colBase = blockIdx.x * 128;
    float acc[4][4][4];
    #pragma unroll
    for (int i = 0; i < 4; ++i)
        #pragma unroll
        for (int j = 0; j < 4; ++j)
            #pragma unroll
            for (int k = 0; k < 4; ++k) acc[i][j][k] = 0.f;

    gemm_mma_body(g_Xhi, g_Xlo, g_WThi[z], g_WTlo[z], rowBase, colBase, sm, acc);

    __nv_bfloat16* Ohi = (z == 0) ? g_Qhi : (z == 1) ? g_Khi : g_Vhi;
    __nv_bfloat16* Olo = (z == 0) ? g_Qlo : (z == 1) ? g_Klo : g_Vlo;
    const float scale = (z == 0) ? 0.125f : 1.0f;

    const int lane = threadIdx.x & 31, w = threadIdx.x >> 5;
    const int wm = (w >> 2) * 64, wn = (w & 3) * 32;
    #pragma unroll
    for (int mi = 0; mi < 4; ++mi)
        #pragma unroll
        for (int nf = 0; nf < 4; ++nf) {
            const int r0 = rowBase + wm + mi * 16 + (lane >> 2);
            const int c0 = colBase + wn + nf * 8 + (lane & 3) * 2;
            const int hh = c0 >> 6, dd = c0 & 63;
            #pragma unroll
            for (int rr = 0; rr < 2; ++rr) {
                const int r = r0 + rr * 8;
                const int b = r >> 11, n = r & (N - 1);
                const size_t idx = (((size_t)(b * H + hh)) * N + n) * DK + dd;
                uint32_t lo;
                const uint32_t hi = packsplit(acc[mi][nf][rr * 2] * scale,
                                              acc[mi][nf][rr * 2 + 1] * scale, lo);
                *reinterpret_cast<uint32_t*>(Ohi + idx) = hi;
                *reinterpret_cast<uint32_t*>(Olo + idx) = lo;
            }
        }
}

// Output projection: attention-out (split) @ Wo -> d_out fp32
__global__ __launch_bounds__(256, 1) void out_mma(float* __restrict__ Cout) {
    extern __shared__ char sm[];
    const int rowBase = blockIdx.y * 128, colBase = blockIdx.x * 128;
    float acc[4][4][4];
    #pragma unroll
    for (int i = 0; i < 4; ++i)
        #pragma unroll
        for (int j = 0; j < 4; ++j)
            #pragma unroll
            for (int k = 0; k < 4; ++k) acc[i][j][k] = 0.f;

    gemm_mma_body(g_AThi, g_ATlo, g_WThi[3], g_WTlo[3], rowBase, colBase, sm, acc);

    const int lane = threadIdx.x & 31, w = threadIdx.x >> 5;
    const int wm = (w >> 2) * 64, wn = (w & 3) * 32;
    #pragma unroll
    for (int mi = 0; mi < 4; ++mi)
        #pragma unroll
        for (int nf = 0; nf < 4; ++nf) {
            const int r0 = rowBase + wm + mi * 16 + (lane >> 2);
            const int c0 = colBase + wn + nf * 8 + (lane & 3) * 2;
            #pragma unroll
            for (int e = 0; e < 4; ++e)
                Cout[(size_t)(r0 + (e >> 1) * 8) * HD + c0 + (e & 1)] = acc[mi][nf][e];
        }
}

// ---------------------------------------------------------------------------
// Precision-split conversion passes
// ---------------------------------------------------------------------------
__global__ void convX(const float* __restrict__ X) {
    const size_t i = ((size_t)blockIdx.x * 256 + threadIdx.x) * 2;
    const float2 v = *(const float2*)(X + i);
    uint32_t lo;
    const uint32_t hi = packsplit(v.x, v.y, lo);
    *reinterpret_cast<uint32_t*>(g_Xhi + i) = hi;
    *reinterpret_cast<uint32_t*>(g_Xlo + i) = lo;
}

__global__ void convW(const float* __restrict__ Wq, const float* __restrict__ Wk,
                      const float* __restrict__ Wv, const float* __restrict__ Wo) {
    const int z = blockIdx.z;
    const float* W = (z == 0) ? Wq : (z == 1) ? Wk : (z == 2) ? Wv : Wo;
    __nv_bfloat16* Th = g_WThi[z];
    __nv_bfloat16* Tl = g_WTlo[z];
    __shared__ float t[32][33];
    const int k0 = blockIdx.x * 32, n0 = blockIdx.y * 32;
    #pragma unroll
    for (int j = 0; j < 32; j += 8)
        t[threadIdx.y + j][threadIdx.x] = W[(size_t)(k0 + threadIdx.y + j) * HD + n0 + threadIdx.x];
    __syncthreads();
    #pragma unroll
    for (int j = 0; j < 32; j += 8) {
        const int n = n0 + threadIdx.y + j, k = k0 + threadIdx.x;
        const float v = t[threadIdx.x][threadIdx.y + j];
        const __nv_bfloat16 h = __float2bfloat16(v);
        Th[(size_t)n * D + k] = h;
        Tl[(size_t)n * D + k] = __float2bfloat16(v - __bfloat162float(h));
    }
}

// ---------------------------------------------------------------------------
// Tensor-core flash attention (causal). 128 q-rows per CTA, 8 warps, each
// warp owns 16 full rows (softmax = quad shuffles only). bf16 hi/lo splits:
// S: Qh*Kh + Qh*Kl + Ql*Kh.   O: Ph*Vh + Ph*Vl + Pl*Vh.
// ---------------------------------------------------------------------------
constexpr int FP     = 144;            // smem pitch (128B data + 16B pad)
constexpr int KVARR  = 64 * FP;        // 9216
constexpr int KVSTG  = 4 * KVARR;      // Kh|Kl|Vh|Vl: 36864
constexpr int QARR   = 128 * FP;       // 18432
constexpr int FSMEM  = 2 * QARR + 2 * KVSTG;   // 110592

__global__ __launch_bounds__(256, 1)
void flash_mma() {
    extern __shared__ char sm[];
    const uint32_t sb = smem_u32(sm);
    const int tid = threadIdx.x, lane = tid & 31, w = tid >> 5;
    const int bh = blockIdx.y;
    const int qt = gridDim.x - 1 - blockIdx.x;        // long blocks first
    const int q0 = qt * 128;
    const int b = bh >> 4, h = bh & (H - 1);
    const int wm = w * 16;

    const __nv_bfloat16* Qh = g_Qhi + (size_t)bh * N * DK;
    const __nv_bfloat16* Ql = g_Qlo + (size_t)bh * N * DK;
    const __nv_bfloat16* Kh = g_Khi + (size_t)bh * N * DK;
    const __nv_bfloat16* Kl = g_Klo + (size_t)bh * N * DK;
    const __nv_bfloat16* Vh = g_Vhi + (size_t)bh * N * DK;
    const __nv_bfloat16* Vl = g_Vlo + (size_t)bh * N * DK;

    const uint32_t qhiS = sb, qloS = sb + QARR, stS = sb + 2 * QARR;

    // Q tile (both arrays), async
    for (int i = tid; i < 1024; i += 256) {
        const int r = i >> 3, ch = i & 7;
        const size_t gi = (size_t)(q0 + r) * DK + ch * 8;
        cp16(qhiS + r * FP + ch * 16, Qh + gi);
        cp16(qloS + r * FP + ch * 16, Ql + gi);
    }
    auto load_kv = [&](int s, int j0) {
        const uint32_t base = stS + s * KVSTG;
        #pragma unroll
        for (int t = 0; t < 2; ++t) {
            const int i = tid + t * 256;
            const int r = i >> 3, ch = i & 7;
            const uint32_t off = r * FP + ch * 16;
            const size_t gi = (size_t)(j0 + r) * DK + ch * 8;
            cp16(base + off,             Kh + gi);
            cp16(base + KVARR + off,     Kl + gi);
            cp16(base + 2 * KVARR + off, Vh + gi);
            cp16(base + 3 * KVARR + off, Vl + gi);
        }
    };
    load_kv(0, 0);
    asm volatile("cp.async.commit_group;" ::: "memory");

    const int jmax = 2 * qt + 1;
    float m0 = -1e30f, m1 = -1e30f, l0 = 0.f, l1 = 0.f;
    float oAcc[8][4];
    #pragma unroll
    for (int i = 0; i < 8; ++i)
        #pragma unroll
        for (int e = 0; e < 4; ++e) oAcc[i][e] = 0.f;

    uint32_t qah[4][4], qal[4][4];
    bool qloaded = false;

    for (int jt = 0; jt <= jmax; ++jt) {
        const int j0 = jt * 64;
        if (jt + 1 <= jmax) load_kv((jt + 1) & 1, (jt + 1) * 64);
        asm volatile("cp.async.commit_group;" ::: "memory");
        asm volatile("cp.async.wait_group 1;" ::: "memory");
        __syncthreads();

        if (!qloaded) {
            #pragma unroll
            for (int kf = 0; kf < 4; ++kf) {
                const uint32_t addr = qhiS + (wm + (lane & 15)) * FP + kf * 32 + (lane >> 4) * 16;
                ldsm4(qah[kf][0], qah[kf][1], qah[kf][2], qah[kf][3], addr);
                ldsm4(qal[kf][0], qal[kf][1], qal[kf][2], qal[kf][3], addr + QARR);
            }
            qloaded = true;
        }

        const uint32_t khS = stS + (jt & 1) * KVSTG;
        const uint32_t vhS = khS + 2 * KVARR;

        // ---- S = Q @ K^T ----
        float s[8][4];
        #pragma unroll
        for (int i = 0; i < 8; ++i)
            #pragma unroll
            for (int e = 0; e < 4; ++e) s[i][e] = 0.f;

        #pragma unroll
        for (int ng = 0; ng < 4; ++ng) {
            uint32_t kb[4][4], klb[4][4];
            #pragma unroll
            for (int kf = 0; kf < 4; ++kf) {
                const uint32_t addr = khS + (ng * 16 + (lane & 7) + ((lane >> 4) << 3)) * FP
                                      + kf * 32 + ((lane >> 3) & 1) * 16;
                ldsm4(kb[kf][0], kb[kf][1], kb[kf][2], kb[kf][3], addr);
                ldsm4(klb[kf][0], klb[kf][1], klb[kf][2], klb[kf][3], addr + KVARR);
            }
            #pragma unroll
            for (int nf = 0; nf < 2; ++nf) {
                float* c = s[ng * 2 + nf];
                #pragma unroll
                for (int kf = 0; kf < 4; ++kf) {
                    mma16816(c, qah[kf][0], qah[kf][1], qah[kf][2], qah[kf][3],
                             kb[kf][nf * 2], kb[kf][nf * 2 + 1]);
                    mma16816(c, qah[kf][0], qah[kf][1], qah[kf][2], qah[kf][3],
                             klb[kf][nf * 2], klb[kf][nf * 2 + 1]);
                    mma16816(c, qal[kf][0], qal[kf][1], qal[kf][2], qal[kf][3],
                             kb[kf][nf * 2], kb[kf][nf * 2 + 1]);
                }
            }
        }

        // ---- causal mask (tiles overlapping this warp's diagonal) ----
        const int gr0 = q0 + wm + (lane >> 2);
        if (j0 + 64 > q0 + wm) {
            #pragma unroll
            for (int ni = 0; ni < 8; ++ni)
                #pragma unroll
                for (int e = 0; e < 4; ++e) {
                    const int col = j0 + ni * 8 + (lane & 3) * 2 + (e & 1);
                    const int row = gr0 + (e >> 1) * 8;
                    if (col > row) s[ni][e] = -1e30f;
                }
        }

        // ---- online softmax (rows gr0, gr0+8) ----
        float rm0 = -1e30f, rm1 = -1e30f;
        #pragma unroll
        for (int ni = 0; ni < 8; ++ni) {
            rm0 = fmaxf(rm0, fmaxf(s[ni][0], s[ni][1]));
            rm1 = fmaxf(rm1, fmaxf(s[ni][2], s[ni][3]));
        }
        rm0 = fmaxf(rm0, __shfl_xor_sync(0xffffffffu, rm0, 1));
        rm0 = fmaxf(rm0, __shfl_xor_sync(0xffffffffu, rm0, 2));
        rm1 = fmaxf(rm1, __shfl_xor_sync(0xffffffffu, rm1, 1));
        rm1 = fmaxf(rm1, __shfl_xor_sync(0xffffffffu, rm1, 2));

        const float mn0 = fmaxf(m0, rm0), mn1 = fmaxf(m1, rm1);
        const float a0 = __expf(m0 - mn0), a1 = __expf(m1 - mn1);
        m0 = mn0; m1 = mn1;

        float rs0 = 0.f, rs1 = 0.f;
        #pragma unroll
        for (int ni = 0; ni < 8; ++ni) {
            s[ni][0] = __expf(s[ni][0] - mn0); rs0 += s[ni][0];
            s[ni][1] = __expf(s[ni][1] - mn0); rs0 += s[ni][1];
            s[ni][2] = __expf(s[ni][2] - mn1); rs1 += s[ni][2];
            s[ni][3] = __expf(s[ni][3] - mn1); rs1 += s[ni][3];
        }
        rs0 += __shfl_xor_sync(0xffffffffu, rs0, 1);
        rs0 += __shfl_xor_sync(0xffffffffu, rs0, 2);
        rs1 += __shfl_xor_sync(0xffffffffu, rs1, 1);
        rs1 += __shfl_xor_sync(0xffffffffu, rs1, 2);
        l0 = l0 * a0 + rs0;
        l1 = l1 * a1 + rs1;

        #pragma unroll
        for (int ni = 0; ni < 8; ++ni) {
            oAcc[ni][0] *= a0; oAcc[ni][1] *= a0;
            oAcc[ni][2] *= a1; oAcc[ni][3] *= a1;
        }

        // ---- P -> bf16 hi/lo A-fragments (register-only) ----
        uint32_t pah[4][4], pal[4][4];
        #pragma unroll
        for (int kf = 0; kf < 4; ++kf) {
            pah[kf][0] = packsplit(s[2 * kf][0],     s[2 * kf][1],     pal[kf][0]);
            pah[kf][1] = packsplit(s[2 * kf][2],     s[2 * kf][3],     pal[kf][1]);
            pah[kf][2] = packsplit(s[2 * kf + 1][0], s[2 * kf + 1][1], pal[kf][2]);
            pah[kf][3] = packsplit(s[2 * kf + 1][2], s[2 * kf + 1][3], pal[kf][3]);
        }

        // ---- O += P @ V  (V frags via trans ldmatrix on row-major V) ----
        #pragma unroll
        for (int ng = 0; ng < 4; ++ng) {
            #pragma unroll
            for (int kf = 0; kf < 4; ++kf) {
                uint32_t vb[4], vlb[4];
                const uint32_t addr = vhS + (kf * 16 + (lane & 15)) * FP
                                      + ng * 32 + (lane >> 4) * 16;
                ldsm4t(vb[0], vb[1], vb[2], vb[3], addr);
                ldsm4t(vlb[0], vlb[1], vlb[2], vlb[3], addr + KVARR);
                #pragma unroll
                for (int nf = 0; nf < 2; ++nf) {
                    float* c = oAcc[ng * 2 + nf];
                    mma16816(c, pah[kf][0], pah[kf][1], pah[kf][2], pah[kf][3],
                             vb[nf * 2], vb[nf * 2 + 1]);
                    mma16816(c, pah[kf][0], pah[kf][1], pah[kf][2], pah[kf][3],
                             vlb[nf * 2], vlb[nf * 2 + 1]);
                    mma16816(c, pal[kf][0], pal[kf][1], pal[kf][2], pal[kf][3],
                             vb[nf * 2], vb[nf * 2 + 1]);
                }
            }
        }
        __syncthreads();
    }

    // ---- epilogue: normalize, split to bf16 hi/lo for output projection ----
    const float inv0 = 1.0f / l0, inv1 = 1.0f / l1;
    const int r0 = q0 + wm + (lane >> 2);
    #pragma unroll
    for (int ni = 0; ni < 8; ++ni) {
        const int col = h * DK + ni * 8 + (lane & 3) * 2;
        uint32_t lo;
        uint32_t hi = packsplit(oAcc[ni][0] * inv0, oAcc[ni][1] * inv0, lo);
        size_t idx = ((size_t)b * N + r0) * HD + col;
        *reinterpret_cast<uint32_t*>(g_AThi + idx) = hi;
        *reinterpret_cast<uint32_t*>(g_ATlo + idx) = lo;
        hi = packsplit(oAcc[ni][2] * inv1, oAcc[ni][3] * inv1, lo);
        idx = ((size_t)b * N + r0 + 8) * HD + col;
        *reinterpret_cast<uint32_t*>(g_AThi + idx) = hi;
        *reinterpret_cast<uint32_t*>(g_ATlo + idx) = lo;
    }
}

// ---------------------------------------------------------------------------
extern "C" void kernel_launch(void* const* d_in, const int* in_sizes, int n_in,
                              void* d_out, int out_size) {
    const float* X  = (const float*)d_in[0];
    // d_in[1] = mask (pure causal -> applied analytically)
    const float* Wq = (const float*)d_in[2];
    const float* Wk = (const float*)d_in[3];
    const float* Wv = (const float*)d_in[4];
    const float* Wo = (const float*)d_in[5];
    float* out = (float*)d_out;

    cudaFuncSetAttribute(qkv_mma,  cudaFuncAttributeMaxDynamicSharedMemorySize, GSMEM);
    cudaFuncSetAttribute(out_mma,  cudaFuncAttributeMaxDynamicSharedMemorySize, GSMEM);
    cudaFuncSetAttribute(flash_mma, cudaFuncAttributeMaxDynamicSharedMemorySize, FSMEM);

    // 0) precision-split conversions
    convX<<<(B * N * D / 2) / 256, 256>>>(X);
    convW<<<dim3(D / 32, HD / 32, 4), dim3(32, 8)>>>(Wq, Wk, Wv, Wo);

    // 1) QKV projections (HMMA), epilogue emits bf16 hi/lo Q/K/V
    qkv_mma<<<dim3(HD / 128, (B * N) / 128, 3), 256, GSMEM>>>();   // (8, 64, 3)

    // 2) causal flash attention on tensor cores
    flash_mma<<<dim3(N / 128, B * H), 256, FSMEM>>>();             // (16, 64)

    // 3) output projection (HMMA)
    out_mma<<<dim3(HD / 128, (B * N) / 128), 256, GSMEM>>>(out);   // (8, 64)
}

// round 8
// speedup vs baseline: 2.7390x; 1.5936x over previous
#include <cuda_runtime.h>
#include <cuda_bf16.h>
#include <cstdint>
#include <math.h>

// Problem constants
constexpr int B  = 4;
constexpr int N  = 2048;
constexpr int D  = 1024;
constexpr int H  = 16;
constexpr int DK = 64;
constexpr int HD = H * DK;   // 1024

// ---------------------------------------------------------------------------
// Scratch (device globals — no allocation allowed)
// ---------------------------------------------------------------------------
__device__ __nv_bfloat16 g_Qhi[(size_t)B * H * N * DK];  // [bh][n][dk], pre-scaled 0.125
__device__ __nv_bfloat16 g_Qlo[(size_t)B * H * N * DK];
__device__ __nv_bfloat16 g_Khi[(size_t)B * H * N * DK];
__device__ __nv_bfloat16 g_Klo[(size_t)B * H * N * DK];
__device__ __nv_bfloat16 g_Vhi[(size_t)B * H * N * DK];
__device__ __nv_bfloat16 g_Vlo[(size_t)B * H * N * DK];
__device__ __nv_bfloat16 g_Xhi[(size_t)B * N * D];       // X split, [m][k]
__device__ __nv_bfloat16 g_Xlo[(size_t)B * N * D];
__device__ __nv_bfloat16 g_WThi[4][(size_t)D * HD];      // W^T split, [n][k] (0=q,1=k,2=v,3=o)
__device__ __nv_bfloat16 g_WTlo[4][(size_t)D * HD];
__device__ __nv_bfloat16 g_AThi[(size_t)B * N * HD];     // attention out split, [m][k]
__device__ __nv_bfloat16 g_ATlo[(size_t)B * N * HD];

// ---------------------------------------------------------------------------
// PTX helpers (generic sm_80+ path — harness PTX targets compute_103, which
// rejects tcgen05/'a'-suffix features; legacy HMMA/ldmatrix/cp.async only)
// ---------------------------------------------------------------------------
__device__ __forceinline__ uint32_t smem_u32(const void* p) {
    uint32_t a;
    asm("{ .reg .u64 t; cvta.to.shared.u64 t, %1; cvt.u32.u64 %0, t; }" : "=r"(a) : "l"(p));
    return a;
}
__device__ __forceinline__ void cp16(uint32_t dst, const void* src) {
    asm volatile("cp.async.cg.shared.global [%0], [%1], 16;" :: "r"(dst), "l"(src));
}
#define CP_COMMIT() asm volatile("cp.async.commit_group;" ::: "memory")
#define CP_WAIT(n)  asm volatile("cp.async.wait_group %0;" :: "n"(n) : "memory")

__device__ __forceinline__ void ldsm4(uint32_t& r0, uint32_t& r1, uint32_t& r2, uint32_t& r3,
                                      uint32_t addr) {
    asm volatile("ldmatrix.sync.aligned.m8n8.x4.shared.b16 {%0,%1,%2,%3}, [%4];"
                 : "=r"(r0), "=r"(r1), "=r"(r2), "=r"(r3) : "r"(addr));
}
__device__ __forceinline__ void ldsm4t(uint32_t& r0, uint32_t& r1, uint32_t& r2, uint32_t& r3,
                                       uint32_t addr) {
    asm volatile("ldmatrix.sync.aligned.m8n8.x4.trans.shared.b16 {%0,%1,%2,%3}, [%4];"
                 : "=r"(r0), "=r"(r1), "=r"(r2), "=r"(r3) : "r"(addr));
}
__device__ __forceinline__ void mma16816(float* c,
                                         uint32_t a0, uint32_t a1, uint32_t a2, uint32_t a3,
                                         uint32_t b0, uint32_t b1) {
    asm volatile("mma.sync.aligned.m16n8k16.row.col.f32.bf16.bf16.f32 "
                 "{%0,%1,%2,%3}, {%4,%5,%6,%7}, {%8,%9}, {%0,%1,%2,%3};"
                 : "+f"(c[0]), "+f"(c[1]), "+f"(c[2]), "+f"(c[3])
                 : "r"(a0), "r"(a1), "r"(a2), "r"(a3), "r"(b0), "r"(b1));
}
// split v0,v1 into packed bf16 hi pair (return) and lo pair (out param)
__device__ __forceinline__ uint32_t packsplit(float v0, float v1, uint32_t& lo) {
    const __nv_bfloat16 h0 = __float2bfloat16(v0);
    const __nv_bfloat16 h1 = __float2bfloat16(v1);
    __nv_bfloat162 hp; hp.x = h0; hp.y = h1;
    __nv_bfloat162 lp;
    lp.x = __float2bfloat16(v0 - __bfloat162float(h0));
    lp.y = __float2bfloat16(v1 - __bfloat162float(h1));
    lo = *reinterpret_cast<uint32_t*>(&lp);
    return *reinterpret_cast<uint32_t*>(&hp);
}

// ---------------------------------------------------------------------------
// bf16-split HMMA GEMM body: C[128,128] = A[128,1024]@B, B given as B^T [n][k].
// 3 products Ah*Bh + Ah*Bl + Al*Bh, fp32 accumulate.
// 4-stage cp.async ring, wait_group 2, single __syncthreads per K-chunk.
// ---------------------------------------------------------------------------
constexpr int APITCH_B = 80;
constexpr int ARR_B    = 128 * APITCH_B;
constexpr int STAGE_B  = 4 * ARR_B;          // 40960
constexpr int GSTAGES  = 4;
constexpr int GSMEM    = GSTAGES * STAGE_B;  // 163840

__device__ __forceinline__ void gemm_mma_body(
    const __nv_bfloat16* __restrict__ Ahi, const __nv_bfloat16* __restrict__ Alo,
    const __nv_bfloat16* __restrict__ Bhi, const __nv_bfloat16* __restrict__ Blo,
    int rowBase, int colBase, char* sm, float acc[4][4][4])
{
    const int tid  = threadIdx.x;
    const int lane = tid & 31;
    const int w    = tid >> 5;
    const int wm   = (w >> 2) * 64;
    const int wn   = (w & 3) * 32;
    const uint32_t sb = smem_u32(sm);

    auto load_stage = [&](int s, int k0) {
        const uint32_t base = sb + s * STAGE_B;
        #pragma unroll
        for (int a = 0; a < 4; ++a) {
            const __nv_bfloat16* src = (a == 0) ? Ahi : (a == 1) ? Alo : (a == 2) ? Bhi : Blo;
            const int rb = (a < 2) ? rowBase : colBase;
            #pragma unroll
            for (int t = 0; t < 2; ++t) {
                const int idx = tid * 2 + t;
                const int r = idx >> 2, ch = idx & 3;
                cp16(base + a * ARR_B + r * APITCH_B + ch * 16,
                     src + (size_t)(rb + r) * D + k0 + ch * 8);
            }
        }
    };

    auto comp = [&](int s) {
        const uint32_t base = sb + s * STAGE_B;
        #pragma unroll
        for (int k16 = 0; k16 < 2; ++k16) {
            uint32_t Ah[4][4], Al[4][4], Bh[2][4], Bl[2][4];
            #pragma unroll
            for (int mi = 0; mi < 4; ++mi) {
                const uint32_t addr = base + (wm + mi * 16 + (lane & 15)) * APITCH_B
                                      + k16 * 32 + (lane >> 4) * 16;
                ldsm4(Ah[mi][0], Ah[mi][1], Ah[mi][2], Ah[mi][3], addr);
                ldsm4(Al[mi][0], Al[mi][1], Al[mi][2], Al[mi][3], addr + ARR_B);
            }
            #pragma unroll
            for (int np = 0; np < 2; ++np) {
                const int nrow = wn + np * 16 + (lane & 7) + ((lane >> 4) << 3);
                const uint32_t addr = base + 2 * ARR_B + nrow * APITCH_B
                                      + k16 * 32 + ((lane >> 3) & 1) * 16;
                ldsm4(Bh[np][0], Bh[np][1], Bh[np][2], Bh[np][3], addr);
                ldsm4(Bl[np][0], Bl[np][1], Bl[np][2], Bl[np][3], addr + ARR_B);
            }
            #pragma unroll
            for (int mi = 0; mi < 4; ++mi)
                #pragma unroll
                for (int nf = 0; nf < 4; ++nf) {
                    const int np = nf >> 1, hh = (nf & 1) * 2;
                    mma16816(acc[mi][nf], Ah[mi][0], Ah[mi][1], Ah[mi][2], Ah[mi][3],
                             Bh[np][hh], Bh[np][hh + 1]);
                    mma16816(acc[mi][nf], Ah[mi][0], Ah[mi][1], Ah[mi][2], Ah[mi][3],
                             Bl[np][hh], Bl[np][hh + 1]);
                    mma16816(acc[mi][nf], Al[mi][0], Al[mi][1], Al[mi][2], Al[mi][3],
                             Bh[np][hh], Bh[np][hh + 1]);
                }
        }
    };

    constexpr int NC = D / 32;   // 32 chunks
    // preamble: fill 3 stages
    load_stage(0, 0);            CP_COMMIT();
    load_stage(1, 32);           CP_COMMIT();
    load_stage(2, 64);           CP_COMMIT();
    for (int c = 0; c < NC; ++c) {
        CP_WAIT(2);              // committed: chunks 0..c+2 -> 0..c complete
        __syncthreads();         // all warps done with comp(c-1); buf (c+3)&3 free
        if (c + 3 < NC) load_stage((c + 3) & 3, (c + 3) * 32);
        CP_COMMIT();
        comp(c & 3);
    }
}

// QKV projection: epilogue writes bf16 hi/lo per-head tensors (Q pre-scaled)
__global__ __launch_bounds__(256, 1) void qkv_mma() {
    extern __shared__ char sm[];
    const int z = blockIdx.z;
    const int rowBase = blockIdx.y * 128, colBase = blockIdx.x * 128;
    float acc[4][4][4];
    #pragma unroll
    for (int i = 0; i < 4; ++i)
        #pragma unroll
        for (int j = 0; j < 4; ++j)
            #pragma unroll
            for (int k = 0; k < 4; ++k) acc[i][j][k] = 0.f;

    gemm_mma_body(g_Xhi, g_Xlo, g_WThi[z], g_WTlo[z], rowBase, colBase, sm, acc);

    __nv_bfloat16* Ohi = (z == 0) ? g_Qhi : (z == 1) ? g_Khi : g_Vhi;
    __nv_bfloat16* Olo = (z == 0) ? g_Qlo : (z == 1) ? g_Klo : g_Vlo;
    const float scale = (z == 0) ? 0.125f : 1.0f;

    const int lane = threadIdx.x & 31, w = threadIdx.x >> 5;
    const int wm = (w >> 2) * 64, wn = (w & 3) * 32;
    #pragma unroll
    for (int mi = 0; mi < 4; ++mi)
        #pragma unroll
        for (int nf = 0; nf < 4; ++nf) {
            const int r0 = rowBase + wm + mi * 16 + (lane >> 2);
            const int c0 = colBase + wn + nf * 8 + (lane & 3) * 2;
            const int hh = c0 >> 6, dd = c0 & 63;
            #pragma unroll
            for (int rr = 0; rr < 2; ++rr) {
                const int r = r0 + rr * 8;
                const int b = r >> 11, n = r & (N - 1);
                const size_t idx = (((size_t)(b * H + hh)) * N + n) * DK + dd;
                uint32_t lo;
                const uint32_t hi = packsplit(acc[mi][nf][rr * 2] * scale,
                                              acc[mi][nf][rr * 2 + 1] * scale, lo);
                *reinterpret_cast<uint32_t*>(Ohi + idx) = hi;
                *reinterpret_cast<uint32_t*>(Olo + idx) = lo;
            }
        }
}

// Output projection: attention-out (split) @ Wo -> d_out fp32
__global__ __launch_bounds__(256, 1) void out_mma(float* __restrict__ Cout) {
    extern __shared__ char sm[];
    const int rowBase = blockIdx.y * 128, colBase = blockIdx.x * 128;
    float acc[4][4][4];
    #pragma unroll
    for (int i = 0; i < 4; ++i)
        #pragma unroll
        for (int j = 0; j < 4; ++j)
            #pragma unroll
            for (int k = 0; k < 4; ++k) acc[i][j][k] = 0.f;

    gemm_mma_body(g_AThi, g_ATlo, g_WThi[3], g_WTlo[3], rowBase, colBase, sm, acc);

    const int lane = threadIdx.x & 31, w = threadIdx.x >> 5;
    const int wm = (w >> 2) * 64, wn = (w & 3) * 32;
    #pragma unroll
    for (int mi = 0; mi < 4; ++mi)
        #pragma unroll
        for (int nf = 0; nf < 4; ++nf) {
            const int r0 = rowBase + wm + mi * 16 + (lane >> 2);
            const int c0 = colBase + wn + nf * 8 + (lane & 3) * 2;
            #pragma unroll
            for (int e = 0; e < 4; ++e)
                Cout[(size_t)(r0 + (e >> 1) * 8) * HD + c0 + (e & 1)] = acc[mi][nf][e];
        }
}

// ---------------------------------------------------------------------------
// Precision-split conversion passes
// ---------------------------------------------------------------------------
__global__ void convX(const float* __restrict__ X) {
    const size_t i = ((size_t)blockIdx.x * 256 + threadIdx.x) * 2;
    const float2 v = *(const float2*)(X + i);
    uint32_t lo;
    const uint32_t hi = packsplit(v.x, v.y, lo);
    *reinterpret_cast<uint32_t*>(g_Xhi + i) = hi;
    *reinterpret_cast<uint32_t*>(g_Xlo + i) = lo;
}

__global__ void convW(const float* __restrict__ Wq, const float* __restrict__ Wk,
                      const float* __restrict__ Wv, const float* __restrict__ Wo) {
    const int z = blockIdx.z;
    const float* W = (z == 0) ? Wq : (z == 1) ? Wk : (z == 2) ? Wv : Wo;
    __nv_bfloat16* Th = g_WThi[z];
    __nv_bfloat16* Tl = g_WTlo[z];
    __shared__ float t[32][33];
    const int k0 = blockIdx.x * 32, n0 = blockIdx.y * 32;
    #pragma unroll
    for (int j = 0; j < 32; j += 8)
        t[threadIdx.y + j][threadIdx.x] = W[(size_t)(k0 + threadIdx.y + j) * HD + n0 + threadIdx.x];
    __syncthreads();
    #pragma unroll
    for (int j = 0; j < 32; j += 8) {
        const int n = n0 + threadIdx.y + j, k = k0 + threadIdx.x;
        const float v = t[threadIdx.x][threadIdx.y + j];
        const __nv_bfloat16 h = __float2bfloat16(v);
        Th[(size_t)n * D + k] = h;
        Tl[(size_t)n * D + k] = __float2bfloat16(v - __bfloat162float(h));
    }
}

// ---------------------------------------------------------------------------
// Tensor-core flash attention (causal). 128 q-rows per CTA, 8 warps, each
// warp owns 16 full rows (softmax = quad shuffles only). bf16 hi/lo splits:
// S: Qh*Kh + Qh*Kl + Ql*Kh.   O: Ph*Vh + Ph*Vl + Pl*Vh.
// 3-stage KV ring, wait_group 1, single __syncthreads per tile.
// ---------------------------------------------------------------------------
constexpr int FP     = 144;            // smem pitch (128B data + 16B pad)
constexpr int KVARR  = 64 * FP;        // 9216
constexpr int KVSTG  = 4 * KVARR;      // Kh|Kl|Vh|Vl: 36864
constexpr int QARR   = 128 * FP;       // 18432
constexpr int FSTAGES = 3;
constexpr int FSMEM  = 2 * QARR + FSTAGES * KVSTG;   // 147456

__global__ __launch_bounds__(256, 1)
void flash_mma() {
    extern __shared__ char sm[];
    const uint32_t sb = smem_u32(sm);
    const int tid = threadIdx.x, lane = tid & 31, w = tid >> 5;
    const int bh = blockIdx.y;
    const int qt = gridDim.x - 1 - blockIdx.x;        // long blocks first
    const int q0 = qt * 128;
    const int b = bh >> 4, h = bh & (H - 1);
    const int wm = w * 16;

    const __nv_bfloat16* Qh = g_Qhi + (size_t)bh * N * DK;
    const __nv_bfloat16* Ql = g_Qlo + (size_t)bh * N * DK;
    const __nv_bfloat16* Kh = g_Khi + (size_t)bh * N * DK;
    const __nv_bfloat16* Kl = g_Klo + (size_t)bh * N * DK;
    const __nv_bfloat16* Vh = g_Vhi + (size_t)bh * N * DK;
    const __nv_bfloat16* Vl = g_Vlo + (size_t)bh * N * DK;

    const uint32_t qhiS = sb, qloS = sb + QARR, stS = sb + 2 * QARR;

    auto load_kv = [&](int s, int j0) {
        const uint32_t base = stS + s * KVSTG;
        #pragma unroll
        for (int t = 0; t < 2; ++t) {
            const int i = tid + t * 256;
            const int r = i >> 3, ch = i & 7;
            const uint32_t off = r * FP + ch * 16;
            const size_t gi = (size_t)(j0 + r) * DK + ch * 8;
            cp16(base + off,             Kh + gi);
            cp16(base + KVARR + off,     Kl + gi);
            cp16(base + 2 * KVARR + off, Vh + gi);
            cp16(base + 3 * KVARR + off, Vl + gi);
        }
    };

    const int jmax = 2 * qt + 1;

    // preamble: Q tile + first KV tile in group 0, second KV tile in group 1
    for (int i = tid; i < 1024; i += 256) {
        const int r = i >> 3, ch = i & 7;
        const size_t gi = (size_t)(q0 + r) * DK + ch * 8;
        cp16(qhiS + r * FP + ch * 16, Qh + gi);
        cp16(qloS + r * FP + ch * 16, Ql + gi);
    }
    load_kv(0, 0);
    CP_COMMIT();
    load_kv(1, 64);
    CP_COMMIT();

    float m0 = -1e30f, m1 = -1e30f, l0 = 0.f, l1 = 0.f;
    float oAcc[8][4];
    #pragma unroll
    for (int i = 0; i < 8; ++i)
        #pragma unroll
        for (int e = 0; e < 4; ++e) oAcc[i][e] = 0.f;

    uint32_t qah[4][4], qal[4][4];
    bool qloaded = false;
    int kvbuf = 0;

    for (int jt = 0; jt <= jmax; ++jt) {
        const int j0 = jt * 64;
        CP_WAIT(1);              // committed: tiles 0..jt+1 -> tile jt ready
        __syncthreads();         // all warps done with tile jt-1; its buf is free
        if (jt + 2 <= jmax) {
            int nb = kvbuf + 2; if (nb >= 3) nb -= 3;
            load_kv(nb, (jt + 2) * 64);
        }
        CP_COMMIT();

        if (!qloaded) {
            #pragma unroll
            for (int kf = 0; kf < 4; ++kf) {
                const uint32_t addr = qhiS + (wm + (lane & 15)) * FP + kf * 32 + (lane >> 4) * 16;
                ldsm4(qah[kf][0], qah[kf][1], qah[kf][2], qah[kf][3], addr);
                ldsm4(qal[kf][0], qal[kf][1], qal[kf][2], qal[kf][3], addr + QARR);
            }
            qloaded = true;
        }

        const uint32_t khS = stS + kvbuf * KVSTG;
        const uint32_t vhS = khS + 2 * KVARR;
        if (++kvbuf == 3) kvbuf = 0;

        // ---- S = Q @ K^T ----
        float s[8][4];
        #pragma unroll
        for (int i = 0; i < 8; ++i)
            #pragma unroll
            for (int e = 0; e < 4; ++e) s[i][e] = 0.f;

        #pragma unroll
        for (int ng = 0; ng < 4; ++ng) {
            uint32_t kb[4][4], klb[4][4];
            #pragma unroll
            for (int kf = 0; kf < 4; ++kf) {
                const uint32_t addr = khS + (ng * 16 + (lane & 7) + ((lane >> 4) << 3)) * FP
                                      + kf * 32 + ((lane >> 3) & 1) * 16;
                ldsm4(kb[kf][0], kb[kf][1], kb[kf][2], kb[kf][3], addr);
                ldsm4(klb[kf][0], klb[kf][1], klb[kf][2], klb[kf][3], addr + KVARR);
            }
            #pragma unroll
            for (int nf = 0; nf < 2; ++nf) {
                float* c = s[ng * 2 + nf];
                #pragma unroll
                for (int kf = 0; kf < 4; ++kf) {
                    mma16816(c, qah[kf][0], qah[kf][1], qah[kf][2], qah[kf][3],
                             kb[kf][nf * 2], kb[kf][nf * 2 + 1]);
                    mma16816(c, qah[kf][0], qah[kf][1], qah[kf][2], qah[kf][3],
                             klb[kf][nf * 2], klb[kf][nf * 2 + 1]);
                    mma16816(c, qal[kf][0], qal[kf][1], qal[kf][2], qal[kf][3],
                             kb[kf][nf * 2], kb[kf][nf * 2 + 1]);
                }
            }
        }

        // ---- causal mask (tiles overlapping this warp's diagonal) ----
        const int gr0 = q0 + wm + (lane >> 2);
        if (j0 + 64 > q0 + wm) {
            #pragma unroll
            for (int ni = 0; ni < 8; ++ni)
                #pragma unroll
                for (int e = 0; e < 4; ++e) {
                    const int col = j0 + ni * 8 + (lane & 3) * 2 + (e & 1);
                    const int row = gr0 + (e >> 1) * 8;
                    if (col > row) s[ni][e] = -1e30f;
                }
        }

        // ---- online softmax (rows gr0, gr0+8) ----
        float rm0 = -1e30f, rm1 = -1e30f;
        #pragma unroll
        for (int ni = 0; ni < 8; ++ni) {
            rm0 = fmaxf(rm0, fmaxf(s[ni][0], s[ni][1]));
            rm1 = fmaxf(rm1, fmaxf(s[ni][2], s[ni][3]));
        }
        rm0 = fmaxf(rm0, __shfl_xor_sync(0xffffffffu, rm0, 1));
        rm0 = fmaxf(rm0, __shfl_xor_sync(0xffffffffu, rm0, 2));
        rm1 = fmaxf(rm1, __shfl_xor_sync(0xffffffffu, rm1, 1));
        rm1 = fmaxf(rm1, __shfl_xor_sync(0xffffffffu, rm1, 2));

        const float mn0 = fmaxf(m0, rm0), mn1 = fmaxf(m1, rm1);
        const float a0 = __expf(m0 - mn0), a1 = __expf(m1 - mn1);
        m0 = mn0; m1 = mn1;

        float rs0 = 0.f, rs1 = 0.f;
        #pragma unroll
        for (int ni = 0; ni < 8; ++ni) {
            s[ni][0] = __expf(s[ni][0] - mn0); rs0 += s[ni][0];
            s[ni][1] = __expf(s[ni][1] - mn0); rs0 += s[ni][1];
            s[ni][2] = __expf(s[ni][2] - mn1); rs1 += s[ni][2];
            s[ni][3] = __expf(s[ni][3] - mn1); rs1 += s[ni][3];
        }
        rs0 += __shfl_xor_sync(0xffffffffu, rs0, 1);
        rs0 += __shfl_xor_sync(0xffffffffu, rs0, 2);
        rs1 += __shfl_xor_sync(0xffffffffu, rs1, 1);
        rs1 += __shfl_xor_sync(0xffffffffu, rs1, 2);
        l0 = l0 * a0 + rs0;
        l1 = l1 * a1 + rs1;

        #pragma unroll
        for (int ni = 0; ni < 8; ++ni) {
            oAcc[ni][0] *= a0; oAcc[ni][1] *= a0;
            oAcc[ni][2] *= a1; oAcc[ni][3] *= a1;
        }

        // ---- P -> bf16 hi/lo A-fragments (register-only) ----
        uint32_t pah[4][4], pal[4][4];
        #pragma unroll
        for (int kf = 0; kf < 4; ++kf) {
            pah[kf][0] = packsplit(s[2 * kf][0],     s[2 * kf][1],     pal[kf][0]);
            pah[kf][1] = packsplit(s[2 * kf][2],     s[2 * kf][3],     pal[kf][1]);
            pah[kf][2] = packsplit(s[2 * kf + 1][0], s[2 * kf + 1][1], pal[kf][2]);
            pah[kf][3] = packsplit(s[2 * kf + 1][2], s[2 * kf + 1][3], pal[kf][3]);
        }

        // ---- O += P @ V  (V frags via trans ldmatrix on row-major V) ----
        #pragma unroll
        for (int ng = 0; ng < 4; ++ng) {
            #pragma unroll
            for (int kf = 0; kf < 4; ++kf) {
                uint32_t vb[4], vlb[4];
                const uint32_t addr = vhS + (kf * 16 + (lane & 15)) * FP
                                      + ng * 32 + (lane >> 4) * 16;
                ldsm4t(vb[0], vb[1], vb[2], vb[3], addr);
                ldsm4t(vlb[0], vlb[1], vlb[2], vlb[3], addr + KVARR);
                #pragma unroll
                for (int nf = 0; nf < 2; ++nf) {
                    float* c = oAcc[ng * 2 + nf];
                    mma16816(c, pah[kf][0], pah[kf][1], pah[kf][2], pah[kf][3],
                             vb[nf * 2], vb[nf * 2 + 1]);
                    mma16816(c, pah[kf][0], pah[kf][1], pah[kf][2], pah[kf][3],
                             vlb[nf * 2], vlb[nf * 2 + 1]);
                    mma16816(c, pal[kf][0], pal[kf][1], pal[kf][2], pal[kf][3],
                             vb[nf * 2], vb[nf * 2 + 1]);
                }
            }
        }
        // no trailing sync: 3-stage ring + top-of-loop barrier covers reuse
    }

    // ---- epilogue: normalize, split to bf16 hi/lo for output projection ----
    const float inv0 = 1.0f / l0, inv1 = 1.0f / l1;
    const int r0 = q0 + wm + (lane >> 2);
    #pragma unroll
    for (int ni = 0; ni < 8; ++ni) {
        const int col = h * DK + ni * 8 + (lane & 3) * 2;
        uint32_t lo;
        uint32_t hi = packsplit(oAcc[ni][0] * inv0, oAcc[ni][1] * inv0, lo);
        size_t idx = ((size_t)b * N + r0) * HD + col;
        *reinterpret_cast<uint32_t*>(g_AThi + idx) = hi;
        *reinterpret_cast<uint32_t*>(g_ATlo + idx) = lo;
        hi = packsplit(oAcc[ni][2] * inv1, oAcc[ni][3] * inv1, lo);
        idx = ((size_t)b * N + r0 + 8) * HD + col;
        *reinterpret_cast<uint32_t*>(g_AThi + idx) = hi;
        *reinterpret_cast<uint32_t*>(g_ATlo + idx) = lo;
    }
}

// ---------------------------------------------------------------------------
extern "C" void kernel_launch(void* const* d_in, const int* in_sizes, int n_in,
                              void* d_out, int out_size) {
    const float* X  = (const float*)d_in[0];
    // d_in[1] = mask (pure causal -> applied analytically)
    const float* Wq = (const float*)d_in[2];
    const float* Wk = (const float*)d_in[3];
    const float* Wv = (const float*)d_in[4];
    const float* Wo = (const float*)d_in[5];
    float* out = (float*)d_out;

    cudaFuncSetAttribute(qkv_mma,   cudaFuncAttributeMaxDynamicSharedMemorySize, GSMEM);
    cudaFuncSetAttribute(out_mma,   cudaFuncAttributeMaxDynamicSharedMemorySize, GSMEM);
    cudaFuncSetAttribute(flash_mma, cudaFuncAttributeMaxDynamicSharedMemorySize, FSMEM);

    // 0) precision-split conversions
    convX<<<(B * N * D / 2) / 256, 256>>>(X);
    convW<<<dim3(D / 32, HD / 32, 4), dim3(32, 8)>>>(Wq, Wk, Wv, Wo);

    // 1) QKV projections (HMMA), epilogue emits bf16 hi/lo Q/K/V
    qkv_mma<<<dim3(HD / 128, (B * N) / 128, 3), 256, GSMEM>>>();   // (8, 64, 3)

    // 2) causal flash attention on tensor cores
    flash_mma<<<dim3(N / 128, B * H), 256, FSMEM>>>();             // (16, 64)

    // 3) output projection (HMMA)
    out_mma<<<dim3(HD / 128, (B * N) / 128), 256, GSMEM>>>(out);   // (8, 64)
}